// round 1
// baseline (speedup 1.0000x reference)
#include <cuda_runtime.h>
#include <cuda_fp16.h>
#include <math.h>

// ---------------- problem constants ----------------
#define NF     1044
#define VOCAB  9396            // NF * 9
#define BATCH  16384
#define CH     261             // fields per smem chunk (1044 = 4*261)
#define NCH    4
#define ROWB   72              // bytes per (field,bucket) row: 32 fp16 + fp32 lin + pad
#define FSTRIDE (9*ROWB)       // 648 bytes per field
#define TBL_BYTES (CH*9*ROWB)  // 169128
#define IDX_OFF  (TBL_BYTES + 8)        // 169136 (16-aligned)
#define IDX_ROW  268                    // 67 words, odd -> conflict-free
#define PRM_OFF  (IDX_OFF + 128*IDX_ROW) // 203440
#define SMEM_SZ  (PRM_OFF + 4624)        // 208064 bytes
#define BN_INV   0.9999950000374997f     // 1/sqrt(1+1e-5)

// scratch table: [VOCAB][72B] = {32 x fp16 (emb@w1 block), fp32 w_lin, 4B pad}
__device__ __align__(16) unsigned char g_tbl[VOCAB * ROWB];

// ---------------- pass 0: build fused table ----------------
__global__ void build_table(const float* __restrict__ emb,
                            const float* __restrict__ w1,
                            const float* __restrict__ w_lin) {
    int warp = (blockIdx.x * blockDim.x + threadIdx.x) >> 5;
    int lane = threadIdx.x & 31;
    if (warp >= NF) return;
    int f = warp;
    float wa = w1[(f*4+0)*32 + lane];
    float wb = w1[(f*4+1)*32 + lane];
    float wc = w1[(f*4+2)*32 + lane];
    float wd = w1[(f*4+3)*32 + lane];
    #pragma unroll
    for (int v = 0; v < 9; v++) {
        int gi = f*9 + v;
        const float* e = emb + gi*4;
        float s = e[0]*wa + e[1]*wb + e[2]*wc + e[3]*wd;
        char* row = (char*)g_tbl + gi*ROWB;
        ((__half*)row)[lane] = __float2half_rn(s);
        if (lane == 0) *(float*)(row + 64) = w_lin[gi];
    }
}

// ---------------- fused main kernel ----------------
// grid 128, block 512. 4 threads per sample (g = tid>>7 owns outputs 8g..8g+7).
#define FIELD(vv) {                                                        \
    const char* row = tb0 + rb + (int)(vv)*ROWB;                           \
    uint2 d0 = *(const uint2*)row;                                         \
    uint2 d1 = *(const uint2*)(row + 8);                                   \
    a0 = __hadd2(a0, *(const __half2*)&d0.x);                              \
    a1 = __hadd2(a1, *(const __half2*)&d0.y);                              \
    a2 = __hadd2(a2, *(const __half2*)&d1.x);                              \
    a3 = __hadd2(a3, *(const __half2*)&d1.y);                              \
    if (g == 0) lin += *(const float*)(row + 64);                          \
    rb += FSTRIDE; }

__global__ void __launch_bounds__(512, 1)
fused_kernel(const float* __restrict__ state,
             const float* __restrict__ b1,  const float* __restrict__ g1,
             const float* __restrict__ be1,
             const float* __restrict__ w2,  const float* __restrict__ b2,
             const float* __restrict__ g2,  const float* __restrict__ be2,
             const float* __restrict__ w3,  const float* __restrict__ b3,
             const float* __restrict__ b_lin,
             float* __restrict__ out) {
    extern __shared__ char smem[];
    const int tid  = threadIdx.x;
    const int slot = tid & 127;       // sample within block
    const int g    = tid >> 7;        // output-quarter group 0..3
    const int s0   = blockIdx.x * 128;
    float* prm = (float*)(smem + PRM_OFF);

    // stage MLP params (read only in epilogue, first __syncthreads covers it)
    for (int i = tid; i < 1152; i += 512) {
        float v;
        if (i < 1024)      v = w2[i];
        else if (i < 1056) v = b2[i-1024];
        else if (i < 1088) v = g2[i-1056];
        else if (i < 1120) v = be2[i-1088];
        else               v = w3[i-1120];
        prm[i] = v;
    }
    if (tid == 0) { prm[1152] = b3[0]; prm[1153] = b_lin[0]; }

    __half2 a0 = __float2half2_rn(0.f), a1 = a0, a2 = a0, a3 = a0;
    float lin = 0.f;
    const uint2* gt = (const uint2*)g_tbl;
    unsigned char* idxb = (unsigned char*)(smem + IDX_OFF);

    for (int c = 0; c < NCH; c++) {
        __syncthreads();
        // load fp16 table chunk (L2-resident source)
        {
            uint2* dst = (uint2*)smem;
            int base = c * (TBL_BYTES/8);
            for (int i = tid; i < TBL_BYTES/8; i += 512) dst[i] = gt[base + i];
        }
        // stage bucket indices (coalesced state reads)
        {
            int f0 = c * CH;
            for (int e2 = tid; e2 < 128*CH; e2 += 512) {
                int r = e2 / CH;
                int f = e2 - r*CH;
                float x = state[(size_t)(s0 + r)*NF + f0 + f];
                int v = (x > 5.0f) ? 8 : (int)(x + 2.0f);
                idxb[r*IDX_ROW + f] = (unsigned char)v;
            }
        }
        __syncthreads();

        const unsigned char* mi = idxb + slot*IDX_ROW;
        const char* tb0 = smem + g*16;     // this group's 16B slice of each row
        int rb = 0;
        int f4 = 0;
        for (; f4 + 4 <= CH; f4 += 4) {
            unsigned int pk = *(const unsigned int*)(mi + f4);
            FIELD(pk & 255u);
            FIELD((pk >> 8) & 255u);
            FIELD((pk >> 16) & 255u);
            FIELD(pk >> 24);
        }
        for (; f4 < CH; f4++) { FIELD(mi[f4]); }   // CH%4 == 1 tail
    }

    // ---------------- epilogue: BN1+ReLU, MLP, sigmoid ----------------
    __syncthreads();   // done with table+idx smem; reuse idx region as h1 buffer
    float2 p01 = __half22float2(a0);
    float2 p23 = __half22float2(a1);
    float2 p45 = __half22float2(a2);
    float2 p67 = __half22float2(a3);
    float pre[8] = {p01.x,p01.y,p23.x,p23.y,p45.x,p45.y,p67.x,p67.y};
    float* h1b = (float*)(smem + IDX_OFF);   // [128][37] fp32, col 32 = lin
    const int j0 = g*8;
    #pragma unroll
    for (int k = 0; k < 8; k++) {
        int j = j0 + k;
        float sc = g1[j] * BN_INV;
        float h  = pre[k]*sc + (b1[j]*sc + be1[j]);
        h1b[slot*37 + j] = fmaxf(h, 0.f);
    }
    if (g == 0) h1b[slot*37 + 32] = lin;
    __syncthreads();

    if (tid < 128) {
        float h[32];
        #pragma unroll
        for (int k = 0; k < 32; k++) h[k] = h1b[tid*37 + k];
        float linv = h1b[tid*37 + 32];
        float acc[32];
        #pragma unroll
        for (int j = 0; j < 32; j++) acc[j] = prm[1024 + j];   // b2
        #pragma unroll 4
        for (int k = 0; k < 32; k++) {
            float xk = h[k];
            #pragma unroll
            for (int j = 0; j < 32; j++) acc[j] += xk * prm[k*32 + j];  // w2
        }
        float x = prm[1152] + prm[1153] + linv;   // b3 + b_lin + lin
        #pragma unroll
        for (int j = 0; j < 32; j++) {
            float h2 = fmaxf(acc[j]*(prm[1056+j]*BN_INV) + prm[1088+j], 0.f);
            x += h2 * prm[1120+j];                // w3
        }
        out[s0 + tid] = 1.0f / (1.0f + expf(-x));
    }
}

// ---------------- launch ----------------
extern "C" void kernel_launch(void* const* d_in, const int* in_sizes, int n_in,
                              void* d_out, int out_size) {
    const float* state = (const float*)d_in[0];
    const float* w_lin = (const float*)d_in[1];
    const float* b_lin = (const float*)d_in[2];
    const float* emb   = (const float*)d_in[3];
    const float* w1    = (const float*)d_in[4];
    const float* b1    = (const float*)d_in[5];
    const float* g1    = (const float*)d_in[6];
    const float* be1   = (const float*)d_in[7];
    const float* w2    = (const float*)d_in[8];
    const float* b2    = (const float*)d_in[9];
    const float* g2    = (const float*)d_in[10];
    const float* be2   = (const float*)d_in[11];
    const float* w3    = (const float*)d_in[12];
    const float* b3    = (const float*)d_in[13];
    float* out = (float*)d_out;

    cudaFuncSetAttribute(fused_kernel,
                         cudaFuncAttributeMaxDynamicSharedMemorySize, SMEM_SZ);

    build_table<<<131, 256>>>(emb, w1, w_lin);
    fused_kernel<<<128, 512, SMEM_SZ>>>(state, b1, g1, be1,
                                        w2, b2, g2, be2, w3, b3, b_lin, out);
}

// round 3
// speedup vs baseline: 1.1758x; 1.1758x over previous
#include <cuda_runtime.h>
#include <cuda_fp16.h>
#include <math.h>

// ---------------- problem constants ----------------
#define NF     1044
#define VOCAB  9396            // NF * 9
#define BATCH  16384
#define CH     261             // fields per smem chunk (1044 = 4*261)
#define NCH    4
#define ROWB   72              // bytes per (field,bucket) row: 32 fp16 + fp32 lin + pad
#define FSTRIDE (9*ROWB)       // 648 bytes per field
#define TBL_BYTES (CH*9*ROWB)  // 169128
#define IDX_OFF  (TBL_BYTES + 8)        // 169136 (16-aligned)
#define IDX_ROW  268                    // 67 words, odd -> conflict-free
#define PRM_OFF  (IDX_OFF + 128*IDX_ROW) // 203440
#define SMEM_SZ  (PRM_OFF + 4624)        // 208064 bytes
#define BN_INV   0.9999950000374997f     // 1/sqrt(1+1e-5)

// scratch table: [VOCAB][72B] = {32 x fp16 (emb@w1 block), fp32 w_lin, 4B pad}
__device__ __align__(16) unsigned char g_tbl[VOCAB * ROWB];

// ---------------- pass 0: build fused table ----------------
__global__ void build_table(const float* __restrict__ emb,
                            const float* __restrict__ w1,
                            const float* __restrict__ w_lin) {
    int warp = (blockIdx.x * blockDim.x + threadIdx.x) >> 5;
    int lane = threadIdx.x & 31;
    if (warp >= NF) return;
    int f = warp;
    float wa = w1[(f*4+0)*32 + lane];
    float wb = w1[(f*4+1)*32 + lane];
    float wc = w1[(f*4+2)*32 + lane];
    float wd = w1[(f*4+3)*32 + lane];
    #pragma unroll
    for (int v = 0; v < 9; v++) {
        int gi = f*9 + v;
        const float* e = emb + gi*4;
        float s = e[0]*wa + e[1]*wb + e[2]*wc + e[3]*wd;
        char* row = (char*)g_tbl + gi*ROWB;
        ((__half*)row)[lane] = __float2half_rn(s);
        if (lane == 0) *(float*)(row + 64) = w_lin[gi];
    }
}

// ---------------- fused main kernel ----------------
// grid 128, block 1024. 8 threads per sample (g = tid>>7 owns outputs 4g..4g+3).
// Each thread gathers an 8-byte slice per field: 1x LDS.64 + 2x HADD2.
#define FIELD(vv) {                                                        \
    const char* row = tb0 + rb + (int)(vv)*ROWB;                           \
    uint2 d0 = *(const uint2*)row;                                         \
    a0 = __hadd2(a0, *(const __half2*)&d0.x);                              \
    a1 = __hadd2(a1, *(const __half2*)&d0.y);                              \
    rb += FSTRIDE; }

__global__ void __launch_bounds__(1024, 1)
fused_kernel(const float* __restrict__ state,
             const float* __restrict__ b1,  const float* __restrict__ g1,
             const float* __restrict__ be1,
             const float* __restrict__ w2,  const float* __restrict__ b2,
             const float* __restrict__ g2,  const float* __restrict__ be2,
             const float* __restrict__ w3,  const float* __restrict__ b3,
             const float* __restrict__ b_lin,
             float* __restrict__ out) {
    extern __shared__ char smem[];
    const int tid  = threadIdx.x;
    const int slot = tid & 127;       // sample within block
    const int g    = tid >> 7;        // output-eighth group 0..7
    const int s0   = blockIdx.x * 128;
    float* prm = (float*)(smem + PRM_OFF);

    // stage MLP params (read only in epilogue; first __syncthreads covers it)
    for (int i = tid; i < 1154; i += 1024) {
        float v;
        if (i < 1024)      v = w2[i];
        else if (i < 1056) v = b2[i-1024];
        else if (i < 1088) v = g2[i-1056];
        else if (i < 1120) v = be2[i-1088];
        else if (i < 1152) v = w3[i-1120];
        else if (i == 1152) v = b3[0];
        else               v = b_lin[0];
        prm[i] = v;
    }

    __half2 a0 = __float2half2_rn(0.f), a1 = a0;
    float lin = 0.f;
    const uint2* gt = (const uint2*)g_tbl;
    unsigned char* idxb = (unsigned char*)(smem + IDX_OFF);

    for (int c = 0; c < NCH; c++) {
        __syncthreads();
        // load fp16 table chunk (L2-resident source)
        {
            uint2* dst = (uint2*)smem;
            int base = c * (TBL_BYTES/8);
            for (int i = tid; i < TBL_BYTES/8; i += 1024) dst[i] = gt[base + i];
        }
        // stage bucket indices (coalesced state reads)
        {
            int f0 = c * CH;
            for (int e2 = tid; e2 < 128*CH; e2 += 1024) {
                int r = e2 / CH;
                int f = e2 - r*CH;
                float x = state[(size_t)(s0 + r)*NF + f0 + f];
                int v = (x > 5.0f) ? 8 : (int)(x + 2.0f);
                idxb[r*IDX_ROW + f] = (unsigned char)v;
            }
        }
        __syncthreads();

        const unsigned char* mi = idxb + slot*IDX_ROW;
        const char* tb0 = smem + g*8;     // this group's 8B slice of each row
        int rb = 0;
        int f4 = 0;
        #pragma unroll 2
        for (; f4 + 4 <= CH; f4 += 4) {
            unsigned int pk = *(const unsigned int*)(mi + f4);
            FIELD(pk & 255u);
            FIELD((pk >> 8) & 255u);
            FIELD((pk >> 16) & 255u);
            FIELD(pk >> 24);
        }
        for (; f4 < CH; f4++) { FIELD(mi[f4]); }   // CH%4 == 1 tail

        // lin accumulation: balanced across the 8 groups (~33 fields each)
        {
            int lo = g * 33;
            int hi = (g == 7) ? CH : lo + 33;
            for (int f = lo; f < hi; f++) {
                int v = mi[f];
                lin += *(const float*)(smem + f*FSTRIDE + v*ROWB + 64);
            }
        }
    }

    // ---------------- epilogue: BN1+ReLU, MLP, sigmoid ----------------
    __syncthreads();   // done with table+idx smem; reuse idx region as h1 buffer
    float2 p01 = __half22float2(a0);
    float2 p23 = __half22float2(a1);
    float pre[4] = {p01.x, p01.y, p23.x, p23.y};
    float* h1b = (float*)(smem + IDX_OFF);   // [128][41] fp32: 32 h, 8 lin partials
    const int j0 = g*4;
    #pragma unroll
    for (int k = 0; k < 4; k++) {
        int j = j0 + k;
        float sc = g1[j] * BN_INV;
        float h  = pre[k]*sc + (b1[j]*sc + be1[j]);
        h1b[slot*41 + j] = fmaxf(h, 0.f);
    }
    h1b[slot*41 + 32 + g] = lin;
    __syncthreads();

    if (tid < 128) {
        const float* hr = h1b + tid*41;
        float linv = 0.f;
        #pragma unroll
        for (int i = 0; i < 8; i++) linv += hr[32 + i];
        float acc[32];
        #pragma unroll
        for (int j = 0; j < 32; j++) acc[j] = prm[1024 + j];   // b2
        for (int k = 0; k < 32; k++) {
            float xk = hr[k];
            #pragma unroll
            for (int j = 0; j < 32; j++) acc[j] += xk * prm[k*32 + j];  // w2
        }
        float x = prm[1152] + prm[1153] + linv;   // b3 + b_lin + lin
        #pragma unroll
        for (int j = 0; j < 32; j++) {
            float h2 = fmaxf(acc[j]*(prm[1056+j]*BN_INV) + prm[1088+j], 0.f);
            x += h2 * prm[1120+j];                // w3
        }
        out[s0 + tid] = 1.0f / (1.0f + expf(-x));
    }
}

// ---------------- launch ----------------
extern "C" void kernel_launch(void* const* d_in, const int* in_sizes, int n_in,
                              void* d_out, int out_size) {
    const float* state = (const float*)d_in[0];
    const float* w_lin = (const float*)d_in[1];
    const float* b_lin = (const float*)d_in[2];
    const float* emb   = (const float*)d_in[3];
    const float* w1    = (const float*)d_in[4];
    const float* b1    = (const float*)d_in[5];
    const float* g1    = (const float*)d_in[6];
    const float* be1   = (const float*)d_in[7];
    const float* w2    = (const float*)d_in[8];
    const float* b2    = (const float*)d_in[9];
    const float* g2    = (const float*)d_in[10];
    const float* be2   = (const float*)d_in[11];
    const float* w3    = (const float*)d_in[12];
    const float* b3    = (const float*)d_in[13];
    float* out = (float*)d_out;

    cudaFuncSetAttribute(fused_kernel,
                         cudaFuncAttributeMaxDynamicSharedMemorySize, SMEM_SZ);

    build_table<<<131, 256>>>(emb, w1, w_lin);
    fused_kernel<<<128, 1024, SMEM_SZ>>>(state, b1, g1, be1,
                                         w2, b2, g2, be2, w3, b3, b_lin, out);
}

// round 4
// speedup vs baseline: 1.3043x; 1.1092x over previous
#include <cuda_runtime.h>
#include <cuda_fp16.h>
#include <math.h>

// ---------------- problem constants ----------------
#define NF     1044
#define VOCAB  9396                 // NF * 9
#define CH     116                  // fields per chunk (1044 = 9*116)
#define NCH    9
#define ROWB   72                   // 32 fp16 + fp32 lin + 4B pad
#define FSTRIDE 648                 // 9*ROWB
#define TBL_CH (CH*FSTRIDE)         // 75168 bytes per chunk
#define IDX_OFF (2*TBL_CH)          // 150336
#define IDX_ROWB 540                // 9 chunks * 60B (58 used), 135 words (odd)
#define PRM_OFF (IDX_OFF + 128*IDX_ROWB)   // 219456
#define SMEM_SZ (PRM_OFF + 4640)           // 224096
#define BN_INV  0.9999950000374997f        // 1/sqrt(1+1e-5)

// fused table: [VOCAB][72B] = {32 x fp16 (emb row @ w1 block), fp32 w_lin, pad}
__device__ __align__(16) unsigned char g_tbl[VOCAB * ROWB];

// ---------------- pass 0: build fused table ----------------
__global__ void build_table(const float* __restrict__ emb,
                            const float* __restrict__ w1,
                            const float* __restrict__ w_lin) {
    int warp = (blockIdx.x * blockDim.x + threadIdx.x) >> 5;
    int lane = threadIdx.x & 31;
    if (warp >= NF) return;
    int f = warp;
    float wa = w1[(f*4+0)*32 + lane];
    float wb = w1[(f*4+1)*32 + lane];
    float wc = w1[(f*4+2)*32 + lane];
    float wd = w1[(f*4+3)*32 + lane];
    #pragma unroll
    for (int v = 0; v < 9; v++) {
        int gi = f*9 + v;
        const float* e = emb + gi*4;
        float s = e[0]*wa + e[1]*wb + e[2]*wc + e[3]*wd;
        char* row = (char*)g_tbl + gi*ROWB;
        ((__half*)row)[lane] = __float2half_rn(s);
        if (lane == 0) *(float*)(row + 64) = w_lin[gi];
    }
}

// ---------------- cp.async helpers ----------------
__device__ __forceinline__ void cp16(unsigned int dst, const void* src) {
    asm volatile("cp.async.cg.shared.global [%0], [%1], 16;" :: "r"(dst), "l"(src));
}
__device__ __forceinline__ void cp_commit() {
    asm volatile("cp.async.commit_group;" ::: "memory");
}
__device__ __forceinline__ void cp_wait_all() {
    asm volatile("cp.async.wait_group 0;" ::: "memory");
}

// 4 gathers (one packed nibble group), batched loads then adds
#define G4(P, OFS) {                                                       \
    unsigned q0 = (P) & 15u, q1 = ((P)>>4) & 15u,                          \
             q2 = ((P)>>8) & 15u, q3 = ((P)>>12) & 15u;                    \
    uint2 d0 = *(const uint2*)(tbw + (OFS)        + q0*72);                \
    uint2 d1 = *(const uint2*)(tbw + (OFS) +  648 + q1*72);                \
    uint2 d2 = *(const uint2*)(tbw + (OFS) + 1296 + q2*72);                \
    uint2 d3 = *(const uint2*)(tbw + (OFS) + 1944 + q3*72);                \
    a0 = __hadd2(a0, *(const __half2*)&d0.x);                              \
    a1 = __hadd2(a1, *(const __half2*)&d0.y);                              \
    a2 = __hadd2(a2, *(const __half2*)&d1.x);                              \
    a3 = __hadd2(a3, *(const __half2*)&d1.y);                              \
    a0 = __hadd2(a0, *(const __half2*)&d2.x);                              \
    a1 = __hadd2(a1, *(const __half2*)&d2.y);                              \
    a2 = __hadd2(a2, *(const __half2*)&d3.x);                              \
    a3 = __hadd2(a3, *(const __half2*)&d3.y); }

__global__ void __launch_bounds__(1024, 1)
fused_kernel(const float* __restrict__ state,
             const float* __restrict__ b1,  const float* __restrict__ g1,
             const float* __restrict__ be1,
             const float* __restrict__ w2,  const float* __restrict__ b2,
             const float* __restrict__ g2,  const float* __restrict__ be2,
             const float* __restrict__ w3,  const float* __restrict__ b3,
             const float* __restrict__ b_lin,
             float* __restrict__ out) {
    extern __shared__ char smem[];
    const int tid  = threadIdx.x;
    const int slot = tid & 127;       // sample within block
    const int g    = tid >> 7;        // output-eighth group 0..7
    const int s0   = blockIdx.x * 128;
    float* prm = (float*)(smem + PRM_OFF);

    // ---- prologue: start chunk-0 table transfer, then stage idx + params ----
    {
        const char* src = (const char*)g_tbl;
        unsigned int dst = (unsigned int)__cvta_generic_to_shared(smem);
        for (int i = tid; i < TBL_CH/16; i += 1024) cp16(dst + i*16, src + i*16);
        cp_commit();
    }

    // stage ALL bucket indices as packed nibbles: row r = sample, 9 chunks x 60B
    {
        int w = tid >> 5, lane = tid & 31;
        #pragma unroll
        for (int q = 0; q < 4; q++) {
            int r = w*4 + q;
            const float2* srow = (const float2*)(state + (size_t)(s0 + r)*NF);
            char* drow = smem + IDX_OFF + r*IDX_ROWB;
            for (int c = 0; c < NCH; c++) {
                #pragma unroll
                for (int bb = lane; bb < 60; bb += 32) {
                    unsigned char byte = 0;
                    if (bb < 58) {
                        float2 xv = srow[c*58 + bb];
                        int v0 = (xv.x > 5.0f) ? 8 : (int)(xv.x + 2.0f);
                        int v1 = (xv.y > 5.0f) ? 8 : (int)(xv.y + 2.0f);
                        byte = (unsigned char)(v0 | (v1 << 4));
                    }
                    drow[c*60 + bb] = byte;
                }
            }
        }
    }

    // stage MLP params
    for (int i = tid; i < 1154; i += 1024) {
        float v;
        if (i < 1024)      v = w2[i];
        else if (i < 1056) v = b2[i-1024];
        else if (i < 1088) v = g2[i-1056];
        else if (i < 1120) v = be2[i-1088];
        else if (i < 1152) v = w3[i-1120];
        else if (i == 1152) v = b3[0];
        else               v = b_lin[0];
        prm[i] = v;
    }

    cp_wait_all();
    __syncthreads();

    __half2 a0 = __float2half2_rn(0.f), a1 = a0, a2 = a0, a3 = a0;
    float lin = 0.f;

    for (int c = 0; c < NCH; c++) {
        // kick off next chunk into the other buffer (overlaps gather below)
        if (c < NCH-1) {
            const char* src = (const char*)g_tbl + (c+1)*TBL_CH;
            unsigned int dst = (unsigned int)__cvta_generic_to_shared(
                                   smem + ((c+1)&1)*TBL_CH);
            for (int i = tid; i < TBL_CH/16; i += 1024) cp16(dst + i*16, src + i*16);
            cp_commit();
        }

        const char* tbuf = smem + (c&1)*TBL_CH;
        const unsigned int* mi =
            (const unsigned int*)(smem + IDX_OFF + slot*IDX_ROWB + c*60);

        // gather: 14 full words (8 fields) + 1 tail word (4 fields)
        {
            const char* tbw = tbuf + g*8;
            #pragma unroll 2
            for (int w = 0; w < 14; w++) {
                unsigned int pk = mi[w];
                G4(pk, 0);
                G4(pk >> 16, 2592);
                tbw += 5184;
            }
            unsigned int pk = mi[14];
            G4(pk, 0);
        }

        // lin accumulation: bytes split across the 8 groups (2x8 + 6x7 = 58)
        {
            const unsigned char* bi = (const unsigned char*)mi;
            int lo = (g < 2) ? g*8 : 16 + (g-2)*7;
            int nb = (g < 2) ? 8 : 7;
            for (int b = lo; b < lo + nb; b++) {
                unsigned int pkb = bi[b];
                const char* fb = tbuf + b*1296 + 64;
                lin += *(const float*)(fb + (pkb & 15u)*72);
                lin += *(const float*)(fb + 648 + (pkb >> 4)*72);
            }
        }

        if (c < NCH-1) cp_wait_all();
        __syncthreads();
    }

    // ---------------- epilogue: BN1+ReLU, MLP, sigmoid ----------------
    a0 = __hadd2(a0, a2);
    a1 = __hadd2(a1, a3);
    float2 p01 = __half22float2(a0);
    float2 p23 = __half22float2(a1);
    float pre[4] = {p01.x, p01.y, p23.x, p23.y};
    float* h1b = (float*)(smem + IDX_OFF);   // reuse idx region: [128][41]
    const int j0 = g*4;
    #pragma unroll
    for (int k = 0; k < 4; k++) {
        int j = j0 + k;
        float sc = g1[j] * BN_INV;
        float h  = pre[k]*sc + (b1[j]*sc + be1[j]);
        h1b[slot*41 + j] = fmaxf(h, 0.f);
    }
    h1b[slot*41 + 32 + g] = lin;
    __syncthreads();

    if (tid < 128) {
        const float* hr = h1b + tid*41;
        float linv = 0.f;
        #pragma unroll
        for (int i = 0; i < 8; i++) linv += hr[32 + i];
        float acc[32];
        #pragma unroll
        for (int j = 0; j < 32; j++) acc[j] = prm[1024 + j];   // b2
        for (int k = 0; k < 32; k++) {
            float xk = hr[k];
            #pragma unroll
            for (int j = 0; j < 32; j++) acc[j] += xk * prm[k*32 + j];  // w2
        }
        float x = prm[1152] + prm[1153] + linv;   // b3 + b_lin + lin
        #pragma unroll
        for (int j = 0; j < 32; j++) {
            float h2 = fmaxf(acc[j]*(prm[1056+j]*BN_INV) + prm[1088+j], 0.f);
            x += h2 * prm[1120+j];                // w3
        }
        out[s0 + tid] = 1.0f / (1.0f + expf(-x));
    }
}

// ---------------- launch ----------------
extern "C" void kernel_launch(void* const* d_in, const int* in_sizes, int n_in,
                              void* d_out, int out_size) {
    const float* state = (const float*)d_in[0];
    const float* w_lin = (const float*)d_in[1];
    const float* b_lin = (const float*)d_in[2];
    const float* emb   = (const float*)d_in[3];
    const float* w1    = (const float*)d_in[4];
    const float* b1    = (const float*)d_in[5];
    const float* g1    = (const float*)d_in[6];
    const float* be1   = (const float*)d_in[7];
    const float* w2    = (const float*)d_in[8];
    const float* b2    = (const float*)d_in[9];
    const float* g2    = (const float*)d_in[10];
    const float* be2   = (const float*)d_in[11];
    const float* w3    = (const float*)d_in[12];
    const float* b3    = (const float*)d_in[13];
    float* out = (float*)d_out;

    cudaFuncSetAttribute(fused_kernel,
                         cudaFuncAttributeMaxDynamicSharedMemorySize, SMEM_SZ);

    build_table<<<131, 256>>>(emb, w1, w_lin);
    fused_kernel<<<128, 1024, SMEM_SZ>>>(state, b1, g1, be1,
                                         w2, b2, g2, be2, w3, b3, b_lin, out);
}

// round 5
// speedup vs baseline: 1.4797x; 1.1345x over previous
#include <cuda_runtime.h>
#include <cuda_fp16.h>
#include <math.h>

// ---------------- problem constants ----------------
#define NF     1044
#define VOCAB  9396                 // NF * 9
#define CH     116                  // fields per chunk (1044 = 9*116)
#define NCH    9
#define ROWB   72                   // 32 fp16 + fp32 lin + 4B pad
#define FSTRIDE 648                 // 9*ROWB
#define TBL_CH (CH*FSTRIDE)         // 75168 bytes per chunk
#define IDX_OFF (2*TBL_CH)          // 150336
#define IDXROW  60                  // bytes per sample per chunk (58 used)
#define IDXBUF  (128*IDXROW)        // 7680
#define MBAR_OFF (IDX_OFF + 2*IDXBUF)      // 165696 (16-aligned)
#define PRM_OFF  (MBAR_OFF + 16)           // 165712
#define SMEM_SZ  (PRM_OFF + 4624)          // 170336
#define BN_INV  0.9999950000374997f        // 1/sqrt(1+1e-5)

// fused table: [VOCAB][72B] = {32 x fp16 (emb row @ w1 block), fp32 w_lin, pad}
__device__ __align__(16) unsigned char g_tbl[VOCAB * ROWB];

// ---------------- pass 0: build fused table ----------------
__global__ void build_table(const float* __restrict__ emb,
                            const float* __restrict__ w1,
                            const float* __restrict__ w_lin) {
    int warp = (blockIdx.x * blockDim.x + threadIdx.x) >> 5;
    int lane = threadIdx.x & 31;
    if (warp >= NF) return;
    int f = warp;
    float wa = w1[(f*4+0)*32 + lane];
    float wb = w1[(f*4+1)*32 + lane];
    float wc = w1[(f*4+2)*32 + lane];
    float wd = w1[(f*4+3)*32 + lane];
    #pragma unroll
    for (int v = 0; v < 9; v++) {
        int gi = f*9 + v;
        const float* e = emb + gi*4;
        float s = e[0]*wa + e[1]*wb + e[2]*wc + e[3]*wd;
        char* row = (char*)g_tbl + gi*ROWB;
        ((__half*)row)[lane] = __float2half_rn(s);
        if (lane == 0) *(float*)(row + 64) = w_lin[gi];
    }
}

// ---------------- mbarrier + TMA bulk helpers ----------------
__device__ __forceinline__ void mbar_init(unsigned m, unsigned cnt) {
    asm volatile("mbarrier.init.shared.b64 [%0], %1;" :: "r"(m), "r"(cnt) : "memory");
}
__device__ __forceinline__ void mbar_expect_tx(unsigned m, unsigned bytes) {
    asm volatile("mbarrier.arrive.expect_tx.shared.b64 _, [%0], %1;"
                 :: "r"(m), "r"(bytes) : "memory");
}
__device__ __forceinline__ void bulk_g2s(unsigned dst, const void* src,
                                         unsigned bytes, unsigned m) {
    asm volatile("cp.async.bulk.shared::cta.global.mbarrier::complete_tx::bytes "
                 "[%0], [%1], %2, [%3];"
                 :: "r"(dst), "l"(src), "r"(bytes), "r"(m) : "memory");
}
__device__ __forceinline__ void mbar_wait(unsigned m, unsigned parity) {
    asm volatile(
        "{\n\t.reg .pred P;\n"
        "WL%=:\n\t"
        "mbarrier.try_wait.parity.acquire.cta.shared::cta.b64 P, [%0], %1, 0x989680;\n\t"
        "@!P bra WL%=;\n\t}"
        :: "r"(m), "r"(parity) : "memory");
}

// 4 gathers (one packed nibble group), batched loads then adds
#define G4(P, OFS) {                                                       \
    unsigned q0 = (P) & 15u, q1 = ((P)>>4) & 15u,                          \
             q2 = ((P)>>8) & 15u, q3 = ((P)>>12) & 15u;                    \
    uint2 d0 = *(const uint2*)(tbw + (OFS)        + q0*72);                \
    uint2 d1 = *(const uint2*)(tbw + (OFS) +  648 + q1*72);                \
    uint2 d2 = *(const uint2*)(tbw + (OFS) + 1296 + q2*72);                \
    uint2 d3 = *(const uint2*)(tbw + (OFS) + 1944 + q3*72);                \
    a0 = __hadd2(a0, *(const __half2*)&d0.x);                              \
    a1 = __hadd2(a1, *(const __half2*)&d0.y);                              \
    a2 = __hadd2(a2, *(const __half2*)&d1.x);                              \
    a3 = __hadd2(a3, *(const __half2*)&d1.y);                              \
    a0 = __hadd2(a0, *(const __half2*)&d2.x);                              \
    a1 = __hadd2(a1, *(const __half2*)&d2.y);                              \
    a2 = __hadd2(a2, *(const __half2*)&d3.x);                              \
    a3 = __hadd2(a3, *(const __half2*)&d3.y); }

__global__ void __launch_bounds__(1024, 1)
fused_kernel(const float* __restrict__ state,
             const float* __restrict__ b1,  const float* __restrict__ g1,
             const float* __restrict__ be1,
             const float* __restrict__ w2,  const float* __restrict__ b2,
             const float* __restrict__ g2,  const float* __restrict__ be2,
             const float* __restrict__ w3,  const float* __restrict__ b3,
             const float* __restrict__ b_lin,
             float* __restrict__ out) {
    extern __shared__ char smem[];
    const int tid  = threadIdx.x;
    const int slot = tid & 127;       // sample within block
    const int g    = tid >> 7;        // output-eighth group 0..7
    const int s0   = blockIdx.x * 128;
    float* prm = (float*)(smem + PRM_OFF);
    const unsigned smem_u32 = (unsigned)__cvta_generic_to_shared(smem);
    const unsigned mbar0 = smem_u32 + MBAR_OFF;
    const unsigned mbar1 = smem_u32 + MBAR_OFF + 8;

    if (tid == 0) { mbar_init(mbar0, 1); mbar_init(mbar1, 1); }
    __syncthreads();
    // prefetch table chunks 0 and 1 via TMA bulk (overlaps staging below)
    if (tid == 0) {
        mbar_expect_tx(mbar0, TBL_CH);
        bulk_g2s(smem_u32, (const char*)g_tbl, TBL_CH, mbar0);
        mbar_expect_tx(mbar1, TBL_CH);
        bulk_g2s(smem_u32 + TBL_CH, (const char*)g_tbl + TBL_CH, TBL_CH, mbar1);
    }

    // stage idx chunk 0 (nibble-packed: float4 -> 2 bytes, STS.16 contiguous)
    {
        char* dstb = smem + IDX_OFF;
        for (int e = tid; e < 128*29; e += 1024) {
            int r = e / 29, u = e - r*29;
            float4 xv = *(const float4*)(state + (size_t)(s0 + r)*NF + u*4);
            int v0 = (xv.x > 5.0f) ? 8 : (int)(xv.x + 2.0f);
            int v1 = (xv.y > 5.0f) ? 8 : (int)(xv.y + 2.0f);
            int v2 = (xv.z > 5.0f) ? 8 : (int)(xv.z + 2.0f);
            int v3 = (xv.w > 5.0f) ? 8 : (int)(xv.w + 2.0f);
            *(unsigned short*)(dstb + r*IDXROW + u*2) =
                (unsigned short)(v0 | (v1<<4) | (v2<<8) | (v3<<12));
        }
    }
    // stage MLP params
    for (int i = tid; i < 1154; i += 1024) {
        float v;
        if (i < 1024)      v = w2[i];
        else if (i < 1056) v = b2[i-1024];
        else if (i < 1088) v = g2[i-1056];
        else if (i < 1120) v = be2[i-1088];
        else if (i < 1152) v = w3[i-1120];
        else if (i == 1152) v = b3[0];
        else               v = b_lin[0];
        prm[i] = v;
    }
    __syncthreads();

    __half2 a0 = __float2half2_rn(0.f), a1 = a0, a2 = a0, a3 = a0;
    float lin = 0.f;

    for (int c = 0; c < NCH; c++) {
        // stage idx for chunk c+1 (LDG latency hides under the gather below)
        if (c + 1 < NCH) {
            const int c1 = c + 1;
            char* dstb = smem + IDX_OFF + (c1&1)*IDXBUF;
            for (int e = tid; e < 128*29; e += 1024) {
                int r = e / 29, u = e - r*29;
                float4 xv = *(const float4*)(state + (size_t)(s0 + r)*NF
                                             + c1*CH + u*4);
                int v0 = (xv.x > 5.0f) ? 8 : (int)(xv.x + 2.0f);
                int v1 = (xv.y > 5.0f) ? 8 : (int)(xv.y + 2.0f);
                int v2 = (xv.z > 5.0f) ? 8 : (int)(xv.z + 2.0f);
                int v3 = (xv.w > 5.0f) ? 8 : (int)(xv.w + 2.0f);
                *(unsigned short*)(dstb + r*IDXROW + u*2) =
                    (unsigned short)(v0 | (v1<<4) | (v2<<8) | (v3<<12));
            }
        }

        // wait for this chunk's table transfer
        mbar_wait((c&1) ? mbar1 : mbar0, (c>>1)&1);

        const char* tbuf = smem + (c&1)*TBL_CH;
        const unsigned int* mi =
            (const unsigned int*)(smem + IDX_OFF + (c&1)*IDXBUF + slot*IDXROW);

        // gather: 14 full words (8 fields each) + tail half-word (4 fields)
        {
            const char* tbw = tbuf + g*8;
            #pragma unroll 2
            for (int w = 0; w < 14; w++) {
                unsigned int pk = mi[w];
                G4(pk, 0);
                G4(pk >> 16, 2592);
                tbw += 5184;
            }
            unsigned int pk = mi[14];
            G4(pk, 0);
        }

        // lin accumulation: bytes split across 8 groups (2x8 + 6x7 = 58)
        {
            const unsigned char* bi = (const unsigned char*)mi;
            int lo = (g < 2) ? g*8 : 16 + (g-2)*7;
            int nb = (g < 2) ? 8 : 7;
            for (int b = lo; b < lo + nb; b++) {
                unsigned int pkb = bi[b];
                const char* fb = tbuf + b*1296 + 64;
                lin += *(const float*)(fb + (pkb & 15u)*72);
                lin += *(const float*)(fb + 648 + (pkb >> 4)*72);
            }
        }

        __syncthreads();   // everyone done reading buf (c&1) and idx (c&1)

        // refill this buffer with chunk c+2
        if (tid == 0 && c + 2 < NCH) {
            unsigned mb = (c&1) ? mbar1 : mbar0;
            mbar_expect_tx(mb, TBL_CH);
            bulk_g2s(smem_u32 + (c&1)*TBL_CH,
                     (const char*)g_tbl + (c+2)*TBL_CH, TBL_CH, mb);
        }
    }

    // ---------------- epilogue: BN1+ReLU, MLP, sigmoid ----------------
    a0 = __hadd2(a0, a2);
    a1 = __hadd2(a1, a3);
    float2 p01 = __half22float2(a0);
    float2 p23 = __half22float2(a1);
    float pre[4] = {p01.x, p01.y, p23.x, p23.y};
    float* h1b = (float*)smem;               // reuse table region: [128][41]
    const int j0 = g*4;
    #pragma unroll
    for (int k = 0; k < 4; k++) {
        int j = j0 + k;
        float sc = g1[j] * BN_INV;
        float h  = pre[k]*sc + (b1[j]*sc + be1[j]);
        h1b[slot*41 + j] = fmaxf(h, 0.f);
    }
    h1b[slot*41 + 32 + g] = lin;
    __syncthreads();

    if (tid < 128) {
        const float* hr = h1b + tid*41;
        float linv = 0.f;
        #pragma unroll
        for (int i = 0; i < 8; i++) linv += hr[32 + i];
        float acc[32];
        #pragma unroll
        for (int j = 0; j < 32; j++) acc[j] = prm[1024 + j];   // b2
        for (int k = 0; k < 32; k++) {
            float xk = hr[k];
            #pragma unroll
            for (int j = 0; j < 32; j++) acc[j] += xk * prm[k*32 + j];  // w2
        }
        float x = prm[1152] + prm[1153] + linv;   // b3 + b_lin + lin
        #pragma unroll
        for (int j = 0; j < 32; j++) {
            float h2 = fmaxf(acc[j]*(prm[1056+j]*BN_INV) + prm[1088+j], 0.f);
            x += h2 * prm[1120+j];                // w3
        }
        out[s0 + tid] = 1.0f / (1.0f + expf(-x));
    }
}

// ---------------- launch ----------------
extern "C" void kernel_launch(void* const* d_in, const int* in_sizes, int n_in,
                              void* d_out, int out_size) {
    const float* state = (const float*)d_in[0];
    const float* w_lin = (const float*)d_in[1];
    const float* b_lin = (const float*)d_in[2];
    const float* emb   = (const float*)d_in[3];
    const float* w1    = (const float*)d_in[4];
    const float* b1    = (const float*)d_in[5];
    const float* g1    = (const float*)d_in[6];
    const float* be1   = (const float*)d_in[7];
    const float* w2    = (const float*)d_in[8];
    const float* b2    = (const float*)d_in[9];
    const float* g2    = (const float*)d_in[10];
    const float* be2   = (const float*)d_in[11];
    const float* w3    = (const float*)d_in[12];
    const float* b3    = (const float*)d_in[13];
    float* out = (float*)d_out;

    cudaFuncSetAttribute(fused_kernel,
                         cudaFuncAttributeMaxDynamicSharedMemorySize, SMEM_SZ);

    build_table<<<131, 256>>>(emb, w1, w_lin);
    fused_kernel<<<128, 1024, SMEM_SZ>>>(state, b1, g1, be1,
                                         w2, b2, g2, be2, w3, b3, b_lin, out);
}